// round 14
// baseline (speedup 1.0000x reference)
#include <cuda_runtime.h>
#include <math.h>

typedef unsigned long long ull;

// ---------------- f32x2 packed helpers (Blackwell) ----------------
__device__ __forceinline__ ull pk2(float lo, float hi) {
    ull r; asm("mov.b64 %0, {%1,%2};" : "=l"(r) : "f"(lo), "f"(hi)); return r;
}
__device__ __forceinline__ float2 upk2(ull v) {
    float2 r; asm("mov.b64 {%0,%1}, %2;" : "=f"(r.x), "=f"(r.y) : "l"(v)); return r;
}
__device__ __forceinline__ ull ffma2(ull a, ull b, ull c) {
    ull d; asm("fma.rn.f32x2 %0, %1, %2, %3;" : "=l"(d) : "l"(a), "l"(b), "l"(c)); return d;
}

// ---------------- device scratch ----------------
__device__ __align__(16) float4 g_feat4[16 * 16384];  // enc output, [quad][y][x] (4 ch)
__device__ __align__(16) float4 g_pred4[512 * 512];   // tail output, (r,g,b,_)
__device__ float g_off[32];                           // per-phase offsets
__device__ float g_A[16 * 512];                       // [ph][k][c]
__device__ float g_B[16 * 512];                       // [ph][c][k]
__device__ __align__(16) ull g_AF2[16 * 16384 * 4];   // A_ph @ feat, [ph][pos][kp] INTERLEAVED
__device__ __align__(16) ull g_TB[1728];              // [ph][tap][o][kp] packed k-pairs
__device__ __align__(16) ull g_TWq[864];              // [q][tap][o][half] packed ch-pairs

// ---------------- K1: enc conv3x3, pad=1, 3->64 ch, quad output ----------------
__global__ void __launch_bounds__(256) enc_kernel(const float* __restrict__ inp,
                                                  const float* __restrict__ w,
                                                  const float* __restrict__ b) {
    __shared__ float sw[108];
    __shared__ float sb[4];
    int tid = threadIdx.x;
    int idx = blockIdx.x * 256 + tid;        // quad*16384 + y*128 + x
    int quad = idx >> 14;
    if (tid < 108) sw[tid] = w[quad * 108 + tid];
    if (tid < 4)   sb[tid] = b[quad * 4 + tid];
    __syncthreads();
    int rem = idx & 16383, y = rem >> 7, x = rem & 127;
    float a0 = sb[0], a1 = sb[1], a2 = sb[2], a3 = sb[3];
#pragma unroll
    for (int ci = 0; ci < 3; ci++) {
        const float* ip = inp + ci * 16384;
#pragma unroll
        for (int ky = 0; ky < 3; ky++) {
            int yy = y + ky - 1;
            if (yy < 0 || yy > 127) continue;
#pragma unroll
            for (int kx = 0; kx < 3; kx++) {
                int xx = x + kx - 1;
                if (xx < 0 || xx > 127) continue;
                float v = __ldg(ip + yy * 128 + xx);
                int t = ci * 9 + ky * 3 + kx;
                a0 += v * sw[t]; a1 += v * sw[27 + t];
                a2 += v * sw[54 + t]; a3 += v * sw[81 + t];
            }
        }
    }
    g_feat4[idx] = make_float4(a0, a1, a2, a3);
}

// ---------------- K2: per-phase MLP -> off, A, B ----------------
__global__ void phase_kernel(const float* __restrict__ w1, const float* __restrict__ b1,
                             const float* __restrict__ w2, const float* __restrict__ b2,
                             const float* __restrict__ rw, const float* __restrict__ rb,
                             const float* __restrict__ ow, const float* __restrict__ ob,
                             const float* __restrict__ wc, const float* __restrict__ we) {
    __shared__ float s1[64], s2[64], sr[4];
    int c = threadIdx.x;
    int ph = blockIdx.x;                 // ph = (y%4)*4 + (x%4)
    float chv = ((ph >> 2) + 0.5f) * 0.25f - 0.5f;
    float cwv = ((ph & 3)  + 0.5f) * 0.25f - 0.5f;
    float e1 = b1[c] + w1[c * 4 + 0] * 0.25f + w1[c * 4 + 1] * 0.25f
                     + w1[c * 4 + 2] * chv   + w1[c * 4 + 3] * cwv;
    s1[c] = fmaxf(e1, 0.f);
    __syncthreads();
    float e2 = b2[c];
    for (int d = 0; d < 64; d++) e2 += w2[c * 64 + d] * s1[d];
    s2[c] = fmaxf(e2, 0.f);
    __syncthreads();
    if (c < 4) {
        float z = rb[c];
        for (int d = 0; d < 64; d++) z += rw[c * 64 + d] * s2[d];
        sr[c] = 1.f / (1.f + expf(-z));
    } else if (c < 6) {
        int o = c - 4;
        float z = ob[o];
        for (int d = 0; d < 64; d++) z += ow[o * 64 + d] * s2[d];
        g_off[ph * 2 + o] = z;
    }
    __syncthreads();
    float r0 = sr[0], r1 = sr[1], r2 = sr[2], r3 = sr[3];
    for (int t = c; t < 512; t += 64) {
        g_A[ph * 512 + t] = r0 * wc[t] + r1 * wc[512 + t] + r2 * wc[1024 + t] + r3 * wc[1536 + t];
        g_B[ph * 512 + t] = r0 * we[t] + r1 * we[512 + t] + r2 * we[1024 + t] + r3 * we[1536 + t];
    }
}

// ---------------- K2b: AF[ph][pos][kp], 8 phases per block, feat read once ----------------
__global__ void __launch_bounds__(256) af_kernel() {
    __shared__ ull sA2[8 * 256];             // [p][k][cpair] for 8 phases
    int tid = threadIdx.x;
    int half = blockIdx.x & 1;               // phase half: 0..7 or 8..15
    int chunk = blockIdx.x >> 1;             // 64 chunks of 256 pos
    for (int t = tid; t < 2048; t += 256)
        sA2[t] = ((const ull*)g_A)[half * 2048 + t];
    __syncthreads();
    int pos = chunk * 256 + tid;

    ull f2[32];
    const ulonglong2* F = (const ulonglong2*)g_feat4;
#pragma unroll
    for (int qd = 0; qd < 16; qd++) {
        ulonglong2 v = __ldg(F + qd * 16384 + pos);
        f2[2 * qd] = v.x; f2[2 * qd + 1] = v.y;
    }
#pragma unroll 1
    for (int p = 0; p < 8; p++) {
        int ph = half * 8 + p;
        ull acc[8];
#pragma unroll
        for (int k = 0; k < 8; k++) acc[k] = 0ULL;
#pragma unroll
        for (int i = 0; i < 32; i++) {
            ull f = f2[i];
#pragma unroll
            for (int k = 0; k < 8; k++)
                acc[k] = ffma2(sA2[p * 256 + k * 32 + i], f, acc[k]);
        }
        float m[8];
#pragma unroll
        for (int k = 0; k < 8; k++) { float2 a = upk2(acc[k]); m[k] = a.x + a.y; }
        ulonglong2* dst = (ulonglong2*)(g_AF2 + ((size_t)ph * 16384 + pos) * 4);
        dst[0] = make_ulonglong2(pk2(m[0], m[1]), pk2(m[2], m[3]));
        dst[1] = make_ulonglong2(pk2(m[4], m[5]), pk2(m[6], m[7]));
    }
}

// ---------------- K2c: parallel pack: TB (8 subs/elem, R11-proven) + quad tail weights ----------------
__global__ void __launch_bounds__(256) pack_kernel(const float* __restrict__ tw) {
    int blk = blockIdx.x;
    int tid = threadIdx.x;
    if (blk < 54) {
        int gt = blk * 256 + tid;
        int e = gt >> 3;              // element 0..1727
        int sub = gt & 7;
        // e = ph*108 + tap*12 + o*4 + kp
        int kp = e & 3, o = (e >> 2) % 3, tap = (e / 12) % 9, ph = e / 108;
        float lo = 0.f, hi = 0.f;
        const float* Bp = g_B + ph * 512;
#pragma unroll
        for (int j = 0; j < 8; j++) {
            int c = sub * 8 + j;
            float wv = __ldg(tw + o * 576 + c * 9 + tap);
            lo += wv * Bp[c * 8 + 2 * kp];
            hi += wv * Bp[c * 8 + 2 * kp + 1];
        }
#pragma unroll
        for (int d = 4; d > 0; d >>= 1) {
            lo += __shfl_down_sync(0xffffffffu, lo, d);
            hi += __shfl_down_sync(0xffffffffu, hi, d);
        }
        if (sub == 0) g_TB[e] = pk2(lo, hi);
    } else {
        int u = (blk - 54) * 256 + tid;       // ((q*9+tap)*3+o)*2+h
        if (u < 864) {
            int h = u & 1, o = (u >> 1) % 3, tap = (u / 6) % 9, q = u / 54;
            int c0 = 4 * q + 2 * h;
            g_TWq[u] = pk2(__ldg(tw + o * 576 + c0 * 9 + tap),
                           __ldg(tw + o * 576 + (c0 + 1) * 9 + tap));
        }
    }
}

// ---------------- K3: FUSED out2 + tail conv, 32x16 tiles, 2 px/thread ----------------
// block: 32x16 output tile; halo 34x18 = 612 px; 16 quad chunks in smem tile.
__global__ void __launch_bounds__(256, 4) fused_kernel(const float* __restrict__ tb) {
    extern __shared__ __align__(16) char shm[];
    float4* sbilW = (float4*)shm;                     // [612]   9792 B
    int*    sMeta = (int*)(shm + 9792);               // [612]   2448 B
    ull*    smid  = (ull*)(shm + 12240);              // [4*612] 19584 B (union)
    ulonglong2* tile = (ulonglong2*)(shm + 12240);    // [18*36] 10368 B (union)
    ull*    sTW   = (ull*)(shm + 12240 + 19584);      // [54]     432 B

    int tid = threadIdx.x;
    int x0 = blockIdx.x * 32, y0 = blockIdx.y * 16;
    int xl = tid & 31, yt = tid >> 5;                 // 32 cols x 8 thread-rows

    // ---- phase 1a: bilinear staging for halo pixels ----
    for (int t = tid; t < 612; t += 256) {
        int r = t / 34, cc = t - r * 34;
        int yy = y0 - 1 + r, xx = x0 - 1 + cc;
        float4 wv = make_float4(0.f, 0.f, 0.f, 0.f);
        int meta = (r * 36 + cc) << 20;
        if (yy >= 0 && yy < 512 && xx >= 0 && xx < 512) {
            int ph = ((yy & 3) << 2) | (xx & 3);
            float offx = __ldg(g_off + 2 * ph), offy = __ldg(g_off + 2 * ph + 1);
            const float C2 = 2.0f / 127.0f;
            float gx = ((xx + 0.5f) * 0.25f - 0.5f) * C2 - 1.0f + offx * C2;
            float gy = ((yy + 0.5f) * 0.25f - 0.5f) * C2 - 1.0f + offy * C2;
            float px = (gx + 1.0f) * 63.5f;
            float py = (gy + 1.0f) * 63.5f;
            float fx = floorf(px), fy = floorf(py);
            float wx1 = px - fx, wx0 = 1.f - wx1;
            float wy1 = py - fy, wy0 = 1.f - wy1;
            int ix0 = (int)fx, iy0 = (int)fy;
            float mx0 = (ix0 >= 0 && ix0 < 128) ? 1.f : 0.f;
            float mx1 = (ix0 + 1 >= 0 && ix0 + 1 < 128) ? 1.f : 0.f;
            float my0 = (iy0 >= 0 && iy0 < 128) ? 1.f : 0.f;
            float my1 = (iy0 + 1 >= 0 && iy0 + 1 < 128) ? 1.f : 0.f;
            int cx0 = min(127, max(0, ix0)), cx1 = min(127, max(0, ix0 + 1));
            int cy0 = min(127, max(0, iy0)), cy1 = min(127, max(0, iy0 + 1));
            wv = make_float4(wy0 * wx0 * my0 * mx0, wy0 * wx1 * my0 * mx1,
                             wy1 * wx0 * my1 * mx0, wy1 * wx1 * my1 * mx1);
            int o00 = (cy0 << 7) | cx0;
            meta |= o00 | ((cx1 - cx0) << 14) | ((cy1 - cy0) << 15) | (ph << 16);
        }
        sbilW[t] = wv;
        sMeta[t] = meta;
    }
    __syncthreads();

    // ---- phase 1b: mid halo = bilinear(AF interleaved): 8 LDG.128 per px ----
    for (int t = tid; t < 612; t += 256) {
        float4 wv = sbilW[t];
        int meta = sMeta[t];
        int o00 = meta & 16383, dx = (meta >> 14) & 1, dy7 = ((meta >> 15) & 1) << 7;
        int ph = (meta >> 16) & 15;
        int o01 = o00 + dx, o10 = o00 + dy7, o11 = o10 + dx;
        ull w00 = pk2(wv.x, wv.x), w01 = pk2(wv.y, wv.y);
        ull w10 = pk2(wv.z, wv.z), w11 = pk2(wv.w, wv.w);
        const ulonglong2* Q = (const ulonglong2*)(g_AF2 + (size_t)ph * 16384 * 4);
        ulonglong2 aL = __ldg(Q + o00 * 2), aH = __ldg(Q + o00 * 2 + 1);
        ull s0 = ffma2(w00, aL.x, 0ULL), s1 = ffma2(w00, aL.y, 0ULL);
        ull s2 = ffma2(w00, aH.x, 0ULL), s3 = ffma2(w00, aH.y, 0ULL);
        aL = __ldg(Q + o01 * 2); aH = __ldg(Q + o01 * 2 + 1);
        s0 = ffma2(w01, aL.x, s0); s1 = ffma2(w01, aL.y, s1);
        s2 = ffma2(w01, aH.x, s2); s3 = ffma2(w01, aH.y, s3);
        aL = __ldg(Q + o10 * 2); aH = __ldg(Q + o10 * 2 + 1);
        s0 = ffma2(w10, aL.x, s0); s1 = ffma2(w10, aL.y, s1);
        s2 = ffma2(w10, aH.x, s2); s3 = ffma2(w10, aH.y, s3);
        aL = __ldg(Q + o11 * 2); aH = __ldg(Q + o11 * 2 + 1);
        s0 = ffma2(w11, aL.x, s0); s1 = ffma2(w11, aL.y, s1);
        s2 = ffma2(w11, aH.x, s2); s3 = ffma2(w11, aH.y, s3);
        smid[t] = s0; smid[612 + t] = s1;
        smid[1224 + t] = s2; smid[1836 + t] = s3;
    }
    __syncthreads();

    // ---- phase 2: mid-conv via TB (rank-8 correction folded into tail) ----
    ull acc[2][3];
#pragma unroll
    for (int i = 0; i < 2; i++)
#pragma unroll
        for (int o = 0; o < 3; o++) acc[i][o] = 0ULL;
#pragma unroll
    for (int i = 0; i < 2; i++) {
        int yo = 2 * yt + i;
#pragma unroll
        for (int ky = 0; ky < 3; ky++) {
#pragma unroll
            for (int kx = 0; kx < 3; kx++) {
                int hidx = (yo + ky) * 34 + xl + kx;
                int ph = (sMeta[hidx] >> 16) & 15;
                const ulonglong2* TBp = (const ulonglong2*)(g_TB + ph * 108 + (ky * 3 + kx) * 12);
                ull m0 = smid[hidx], m1 = smid[612 + hidx];
                ull m2 = smid[1224 + hidx], m3 = smid[1836 + hidx];
                ulonglong2 t0 = __ldg(TBp + 0), t1 = __ldg(TBp + 1);
                acc[i][0] = ffma2(t0.x, m0, acc[i][0]); acc[i][0] = ffma2(t0.y, m1, acc[i][0]);
                acc[i][0] = ffma2(t1.x, m2, acc[i][0]); acc[i][0] = ffma2(t1.y, m3, acc[i][0]);
                t0 = __ldg(TBp + 2); t1 = __ldg(TBp + 3);
                acc[i][1] = ffma2(t0.x, m0, acc[i][1]); acc[i][1] = ffma2(t0.y, m1, acc[i][1]);
                acc[i][1] = ffma2(t1.x, m2, acc[i][1]); acc[i][1] = ffma2(t1.y, m3, acc[i][1]);
                t0 = __ldg(TBp + 4); t1 = __ldg(TBp + 5);
                acc[i][2] = ffma2(t0.x, m0, acc[i][2]); acc[i][2] = ffma2(t0.y, m1, acc[i][2]);
                acc[i][2] = ffma2(t1.x, m2, acc[i][2]); acc[i][2] = ffma2(t1.y, m3, acc[i][2]);
            }
        }
    }
    __syncthreads();   // release smid region for tile reuse

    // ---- phase 3: 16 quad chunks: stage out2 tile (bil of feat), conv ----
    for (int q = 0; q < 16; q++) {
        if (tid < 54) sTW[tid] = __ldg(g_TWq + q * 54 + tid);
        const ulonglong2* F = (const ulonglong2*)g_feat4 + q * 16384;
        for (int t = tid; t < 612; t += 256) {
            float4 wv = sbilW[t];
            int meta = sMeta[t];
            int o00 = meta & 16383, dx = (meta >> 14) & 1, dy7 = ((meta >> 15) & 1) << 7;
            int o01 = o00 + dx, o10 = o00 + dy7, o11 = o10 + dx;
            ull w00 = pk2(wv.x, wv.x), w01 = pk2(wv.y, wv.y);
            ull w10 = pk2(wv.z, wv.z), w11 = pk2(wv.w, wv.w);
            ulonglong2 v00 = __ldg(F + o00), v01 = __ldg(F + o01);
            ulonglong2 v10 = __ldg(F + o10), v11 = __ldg(F + o11);
            ull lo = ffma2(w00, v00.x, 0ULL), hi = ffma2(w00, v00.y, 0ULL);
            lo = ffma2(w01, v01.x, lo); hi = ffma2(w01, v01.y, hi);
            lo = ffma2(w10, v10.x, lo); hi = ffma2(w10, v10.y, hi);
            lo = ffma2(w11, v11.x, lo); hi = ffma2(w11, v11.y, hi);
            tile[(meta >> 20) & 2047] = make_ulonglong2(lo, hi);
        }
        __syncthreads();
#pragma unroll
        for (int ky = 0; ky < 3; ky++) {
#pragma unroll
            for (int kx = 0; kx < 3; kx++) {
                const ull* W = sTW + (ky * 3 + kx) * 6;
                ull w0l = W[0], w0h = W[1], w1l = W[2], w1h = W[3], w2l = W[4], w2h = W[5];
#pragma unroll
                for (int i = 0; i < 2; i++) {
                    ulonglong2 v = tile[(2 * yt + i + ky) * 36 + xl + kx];
                    acc[i][0] = ffma2(w0l, v.x, acc[i][0]); acc[i][0] = ffma2(w0h, v.y, acc[i][0]);
                    acc[i][1] = ffma2(w1l, v.x, acc[i][1]); acc[i][1] = ffma2(w1h, v.y, acc[i][1]);
                    acc[i][2] = ffma2(w2l, v.x, acc[i][2]); acc[i][2] = ffma2(w2h, v.y, acc[i][2]);
                }
            }
        }
        __syncthreads();
    }

    float tb0 = __ldg(tb), tb1 = __ldg(tb + 1), tb2 = __ldg(tb + 2);
#pragma unroll
    for (int i = 0; i < 2; i++) {
        int yo = 2 * yt + i;
        float2 a0 = upk2(acc[i][0]), a1 = upk2(acc[i][1]), a2 = upk2(acc[i][2]);
        g_pred4[(y0 + yo) * 512 + x0 + xl] =
            make_float4(tb0 + a0.x + a0.y, tb1 + a1.x + a1.y, tb2 + a2.x + a2.y, 0.f);
    }
}

// ---------------- K5: query gather ----------------
__global__ void gather_kernel(const float* __restrict__ coord,
                              const float* __restrict__ cell,
                              float* __restrict__ out) {
    int q = blockIdx.x * 256 + threadIdx.x;
    float2 cd = __ldg((const float2*)coord + q);
    float2 cl = __ldg((const float2*)cell + q);
    const float LO = -0.999999f, HI = 0.999999f;
    float gyq = fminf(fmaxf(cd.x - cl.x * 0.5f + 1e-6f, LO), HI);
    float gxq = fminf(fmaxf(cd.y - cl.y * 0.5f + 1e-6f, LO), HI);
    int xi = (int)rintf((gxq + 1.0f) * 0.5f * 511.0f);
    int yi = (int)rintf((gyq + 1.0f) * 0.5f * 511.0f);
    xi = min(511, max(0, xi));
    yi = min(511, max(0, yi));
    float4 v = __ldg(&g_pred4[(yi << 9) + xi]);
    out[q * 3 + 0] = v.x;
    out[q * 3 + 1] = v.y;
    out[q * 3 + 2] = v.z;
}

// ---------------- launch ----------------
extern "C" void kernel_launch(void* const* d_in, const int* in_sizes, int n_in,
                              void* d_out, int out_size) {
    const float* inp   = (const float*)d_in[0];
    const float* coord = (const float*)d_in[1];
    const float* cell  = (const float*)d_in[2];
    const float* enc_w = (const float*)d_in[3];
    const float* enc_b = (const float*)d_in[4];
    const float* w1    = (const float*)d_in[5];
    const float* b1    = (const float*)d_in[6];
    const float* w2    = (const float*)d_in[7];
    const float* b2    = (const float*)d_in[8];
    const float* rw    = (const float*)d_in[9];
    const float* rb    = (const float*)d_in[10];
    const float* ow    = (const float*)d_in[11];
    const float* ob    = (const float*)d_in[12];
    const float* tw    = (const float*)d_in[13];
    const float* tb    = (const float*)d_in[14];
    const float* wc    = (const float*)d_in[15];
    const float* we    = (const float*)d_in[16];
    float* out = (float*)d_out;

    const int SHM = 9792 + 2448 + 19584 + 432;   // 32256 B
    cudaFuncSetAttribute(fused_kernel, cudaFuncAttributeMaxDynamicSharedMemorySize, SHM);

    enc_kernel<<<1024, 256>>>(inp, enc_w, enc_b);
    phase_kernel<<<16, 64>>>(w1, b1, w2, b2, rw, rb, ow, ob, wc, we);
    af_kernel<<<128, 256>>>();
    pack_kernel<<<58, 256>>>(tw);
    fused_kernel<<<dim3(16, 32), 256, SHM>>>(tb);
    gather_kernel<<<1024, 256>>>(coord, cell, out);
}

// round 15
// speedup vs baseline: 1.0368x; 1.0368x over previous
#include <cuda_runtime.h>
#include <math.h>

typedef unsigned long long ull;

// ---------------- f32x2 packed helpers (Blackwell) ----------------
__device__ __forceinline__ ull pk2(float lo, float hi) {
    ull r; asm("mov.b64 %0, {%1,%2};" : "=l"(r) : "f"(lo), "f"(hi)); return r;
}
__device__ __forceinline__ float2 upk2(ull v) {
    float2 r; asm("mov.b64 {%0,%1}, %2;" : "=f"(r.x), "=f"(r.y) : "l"(v)); return r;
}
__device__ __forceinline__ ull ffma2(ull a, ull b, ull c) {
    ull d; asm("fma.rn.f32x2 %0, %1, %2, %3;" : "=l"(d) : "l"(a), "l"(b), "l"(c)); return d;
}

// ---------------- device scratch ----------------
__device__ __align__(16) float4 g_feat4[16 * 16384];  // enc output, [quad][y][x] (4 ch)
__device__ __align__(16) float4 g_pred4[512 * 512];   // tail output, (r,g,b,_)
__device__ float g_off[32];                           // per-phase offsets
__device__ float g_A[16 * 512];                       // [ph][k][c]
__device__ float g_B[16 * 512];                       // [ph][c][k]
__device__ __align__(16) ull g_AF2[16 * 4 * 16384];   // A_ph @ feat, [ph][kpair][pos]
__device__ __align__(16) ull g_TB[1728];              // [ph][tap][o][kp] packed k-pairs
__device__ __align__(16) ull g_TWq[864];              // [q][tap][o][half] packed ch-pairs

// ---------------- K1: enc conv3x3, pad=1, 3->64 ch, quad output ----------------
__global__ void __launch_bounds__(256) enc_kernel(const float* __restrict__ inp,
                                                  const float* __restrict__ w,
                                                  const float* __restrict__ b) {
    __shared__ float sw[108];
    __shared__ float sb[4];
    int tid = threadIdx.x;
    int idx = blockIdx.x * 256 + tid;        // quad*16384 + y*128 + x
    int quad = idx >> 14;
    if (tid < 108) sw[tid] = w[quad * 108 + tid];
    if (tid < 4)   sb[tid] = b[quad * 4 + tid];
    __syncthreads();
    int rem = idx & 16383, y = rem >> 7, x = rem & 127;
    float a0 = sb[0], a1 = sb[1], a2 = sb[2], a3 = sb[3];
#pragma unroll
    for (int ci = 0; ci < 3; ci++) {
        const float* ip = inp + ci * 16384;
#pragma unroll
        for (int ky = 0; ky < 3; ky++) {
            int yy = y + ky - 1;
            if (yy < 0 || yy > 127) continue;
#pragma unroll
            for (int kx = 0; kx < 3; kx++) {
                int xx = x + kx - 1;
                if (xx < 0 || xx > 127) continue;
                float v = __ldg(ip + yy * 128 + xx);
                int t = ci * 9 + ky * 3 + kx;
                a0 += v * sw[t]; a1 += v * sw[27 + t];
                a2 += v * sw[54 + t]; a3 += v * sw[81 + t];
            }
        }
    }
    g_feat4[idx] = make_float4(a0, a1, a2, a3);
}

// ---------------- K2: per-phase MLP -> off, A, B ----------------
__global__ void phase_kernel(const float* __restrict__ w1, const float* __restrict__ b1,
                             const float* __restrict__ w2, const float* __restrict__ b2,
                             const float* __restrict__ rw, const float* __restrict__ rb,
                             const float* __restrict__ ow, const float* __restrict__ ob,
                             const float* __restrict__ wc, const float* __restrict__ we) {
    __shared__ float s1[64], s2[64], sr[4];
    int c = threadIdx.x;
    int ph = blockIdx.x;                 // ph = (y%4)*4 + (x%4)
    float chv = ((ph >> 2) + 0.5f) * 0.25f - 0.5f;
    float cwv = ((ph & 3)  + 0.5f) * 0.25f - 0.5f;
    float e1 = b1[c] + w1[c * 4 + 0] * 0.25f + w1[c * 4 + 1] * 0.25f
                     + w1[c * 4 + 2] * chv   + w1[c * 4 + 3] * cwv;
    s1[c] = fmaxf(e1, 0.f);
    __syncthreads();
    float e2 = b2[c];
    for (int d = 0; d < 64; d++) e2 += w2[c * 64 + d] * s1[d];
    s2[c] = fmaxf(e2, 0.f);
    __syncthreads();
    if (c < 4) {
        float z = rb[c];
        for (int d = 0; d < 64; d++) z += rw[c * 64 + d] * s2[d];
        sr[c] = 1.f / (1.f + expf(-z));
    } else if (c < 6) {
        int o = c - 4;
        float z = ob[o];
        for (int d = 0; d < 64; d++) z += ow[o * 64 + d] * s2[d];
        g_off[ph * 2 + o] = z;
    }
    __syncthreads();
    float r0 = sr[0], r1 = sr[1], r2 = sr[2], r3 = sr[3];
    for (int t = c; t < 512; t += 64) {
        g_A[ph * 512 + t] = r0 * wc[t] + r1 * wc[512 + t] + r2 * wc[1024 + t] + r3 * wc[1536 + t];
        g_B[ph * 512 + t] = r0 * we[t] + r1 * we[512 + t] + r2 * we[1024 + t] + r3 * we[1536 + t];
    }
}

// ---------------- K2b: combined prep: AF (8 phases/block, feat once) + TB/TWq pack ----------------
// blocks 0..127: AF.  blocks 128..181: TB pack.  blocks 182..185: TWq pack.
__global__ void __launch_bounds__(256) prep_kernel(const float* __restrict__ tw) {
    int blk = blockIdx.x;
    int tid = threadIdx.x;
    if (blk < 128) {
        __shared__ ull sA2[8 * 256];             // [p][k][cpair] for 8 phases
        int half = blk & 1;                      // phase half: 0..7 or 8..15
        int chunk = blk >> 1;                    // 64 chunks of 256 pos
        for (int t = tid; t < 2048; t += 256)
            sA2[t] = ((const ull*)g_A)[half * 2048 + t];
        __syncthreads();
        int pos = chunk * 256 + tid;

        ull f2[32];
        const ulonglong2* F = (const ulonglong2*)g_feat4;
#pragma unroll
        for (int qd = 0; qd < 16; qd++) {
            ulonglong2 v = __ldg(F + qd * 16384 + pos);
            f2[2 * qd] = v.x; f2[2 * qd + 1] = v.y;
        }
#pragma unroll 1
        for (int p = 0; p < 8; p++) {
            int ph = half * 8 + p;
            ull acc[8];
#pragma unroll
            for (int k = 0; k < 8; k++) acc[k] = 0ULL;
#pragma unroll
            for (int i = 0; i < 32; i++) {
                ull f = f2[i];
#pragma unroll
                for (int k = 0; k < 8; k++)
                    acc[k] = ffma2(sA2[p * 256 + k * 32 + i], f, acc[k]);
            }
            float m[8];
#pragma unroll
            for (int k = 0; k < 8; k++) { float2 a = upk2(acc[k]); m[k] = a.x + a.y; }
#pragma unroll
            for (int kp = 0; kp < 4; kp++)
                g_AF2[((size_t)(ph * 4 + kp)) * 16384 + pos] = pk2(m[2 * kp], m[2 * kp + 1]);
        }
    } else if (blk < 182) {
        int gt = (blk - 128) * 256 + tid;
        int e = gt >> 3;              // element 0..1727
        int sub = gt & 7;
        // e = ph*108 + tap*12 + o*4 + kp
        int kp = e & 3, o = (e >> 2) % 3, tap = (e / 12) % 9, ph = e / 108;
        float lo = 0.f, hi = 0.f;
        const float* Bp = g_B + ph * 512;
#pragma unroll
        for (int j = 0; j < 8; j++) {
            int c = sub * 8 + j;
            float wv = __ldg(tw + o * 576 + c * 9 + tap);
            lo += wv * Bp[c * 8 + 2 * kp];
            hi += wv * Bp[c * 8 + 2 * kp + 1];
        }
#pragma unroll
        for (int d = 4; d > 0; d >>= 1) {
            lo += __shfl_down_sync(0xffffffffu, lo, d);
            hi += __shfl_down_sync(0xffffffffu, hi, d);
        }
        if (sub == 0) g_TB[e] = pk2(lo, hi);
    } else {
        int u = (blk - 182) * 256 + tid;      // ((q*9+tap)*3+o)*2+h
        if (u < 864) {
            int h = u & 1, o = (u >> 1) % 3, tap = (u / 6) % 9, q = u / 54;
            int c0 = 4 * q + 2 * h;
            g_TWq[u] = pk2(__ldg(tw + o * 576 + c0 * 9 + tap),
                           __ldg(tw + o * 576 + (c0 + 1) * 9 + tap));
        }
    }
}

// ---------------- K3: FUSED out2 + tail conv (R9-proven, untouched) ----------------
// block: 64x16 output tile; halo 66x18 = 1188 px; 16 quad chunks in smem tile.
__global__ void __launch_bounds__(256, 3) fused_kernel(const float* __restrict__ tb) {
    extern __shared__ __align__(16) char shm[];
    float4* sbilW = (float4*)shm;                     // [1188]  19008 B
    int*    sMeta = (int*)(shm + 19008);              // [1188]   4752 B
    ull*    smid  = (ull*)(shm + 23760);              // [4*1188] 38016 B (union)
    ulonglong2* tile = (ulonglong2*)(shm + 23760);    // [18*68]  19584 B (union)
    ull*    sTW   = (ull*)(shm + 23760 + 19584);      // [54]

    int tid = threadIdx.x;
    int x0 = blockIdx.x * 64, y0 = blockIdx.y * 16;
    int xl = tid & 63, yt = tid >> 6;

    // ---- phase 1a: bilinear staging for halo pixels ----
    for (int t = tid; t < 1188; t += 256) {
        int r = t / 66, cc = t - r * 66;
        int yy = y0 - 1 + r, xx = x0 - 1 + cc;
        float4 wv = make_float4(0.f, 0.f, 0.f, 0.f);
        int meta = (r * 68 + cc) << 20;
        if (yy >= 0 && yy < 512 && xx >= 0 && xx < 512) {
            int ph = ((yy & 3) << 2) | (xx & 3);
            float offx = __ldg(g_off + 2 * ph), offy = __ldg(g_off + 2 * ph + 1);
            const float C2 = 2.0f / 127.0f;
            float gx = ((xx + 0.5f) * 0.25f - 0.5f) * C2 - 1.0f + offx * C2;
            float gy = ((yy + 0.5f) * 0.25f - 0.5f) * C2 - 1.0f + offy * C2;
            float px = (gx + 1.0f) * 63.5f;
            float py = (gy + 1.0f) * 63.5f;
            float fx = floorf(px), fy = floorf(py);
            float wx1 = px - fx, wx0 = 1.f - wx1;
            float wy1 = py - fy, wy0 = 1.f - wy1;
            int ix0 = (int)fx, iy0 = (int)fy;
            float mx0 = (ix0 >= 0 && ix0 < 128) ? 1.f : 0.f;
            float mx1 = (ix0 + 1 >= 0 && ix0 + 1 < 128) ? 1.f : 0.f;
            float my0 = (iy0 >= 0 && iy0 < 128) ? 1.f : 0.f;
            float my1 = (iy0 + 1 >= 0 && iy0 + 1 < 128) ? 1.f : 0.f;
            int cx0 = min(127, max(0, ix0)), cx1 = min(127, max(0, ix0 + 1));
            int cy0 = min(127, max(0, iy0)), cy1 = min(127, max(0, iy0 + 1));
            wv = make_float4(wy0 * wx0 * my0 * mx0, wy0 * wx1 * my0 * mx1,
                             wy1 * wx0 * my1 * mx0, wy1 * wx1 * my1 * mx1);
            int o00 = (cy0 << 7) | cx0;
            meta |= o00 | ((cx1 - cx0) << 14) | ((cy1 - cy0) << 15) | (ph << 16);
        }
        sbilW[t] = wv;
        sMeta[t] = meta;
    }
    __syncthreads();

    // ---- phase 1b: mid halo = bilinear(AF) ----
    for (int t = tid; t < 1188; t += 256) {
        float4 wv = sbilW[t];
        int meta = sMeta[t];
        int o00 = meta & 16383, dx = (meta >> 14) & 1, dy7 = ((meta >> 15) & 1) << 7;
        int ph = (meta >> 16) & 15;
        ull w00 = pk2(wv.x, wv.x), w01 = pk2(wv.y, wv.y);
        ull w10 = pk2(wv.z, wv.z), w11 = pk2(wv.w, wv.w);
        int o01 = o00 + dx, o10 = o00 + dy7, o11 = o10 + dx;
        const ull* AFp = g_AF2 + ph * 4 * 16384;
#pragma unroll
        for (int kp = 0; kp < 4; kp++) {
            const ull* Q = AFp + kp * 16384;
            ull a = ffma2(w00, __ldg(Q + o00), 0ULL);
            ull bq = ffma2(w01, __ldg(Q + o01), 0ULL);
            a = ffma2(w10, __ldg(Q + o10), a);
            bq = ffma2(w11, __ldg(Q + o11), bq);
            float2 s1 = upk2(a), s2 = upk2(bq);
            smid[kp * 1188 + t] = pk2(s1.x + s2.x, s1.y + s2.y);
        }
    }
    __syncthreads();

    // ---- phase 2: mid-conv via TB (rank-8 correction folded into tail) ----
    ull acc[4][3];
#pragma unroll
    for (int i = 0; i < 4; i++)
#pragma unroll
        for (int o = 0; o < 3; o++) acc[i][o] = 0ULL;
#pragma unroll
    for (int i = 0; i < 4; i++) {
        int yo = 4 * yt + i;
#pragma unroll
        for (int ky = 0; ky < 3; ky++) {
#pragma unroll
            for (int kx = 0; kx < 3; kx++) {
                int hidx = (yo + ky) * 66 + xl + kx;
                int ph = (sMeta[hidx] >> 16) & 15;
                const ulonglong2* TBp = (const ulonglong2*)(g_TB + ph * 108 + (ky * 3 + kx) * 12);
                ull m0 = smid[hidx], m1 = smid[1188 + hidx];
                ull m2 = smid[2376 + hidx], m3 = smid[3564 + hidx];
                ulonglong2 t0 = __ldg(TBp + 0), t1 = __ldg(TBp + 1);
                acc[i][0] = ffma2(t0.x, m0, acc[i][0]); acc[i][0] = ffma2(t0.y, m1, acc[i][0]);
                acc[i][0] = ffma2(t1.x, m2, acc[i][0]); acc[i][0] = ffma2(t1.y, m3, acc[i][0]);
                t0 = __ldg(TBp + 2); t1 = __ldg(TBp + 3);
                acc[i][1] = ffma2(t0.x, m0, acc[i][1]); acc[i][1] = ffma2(t0.y, m1, acc[i][1]);
                acc[i][1] = ffma2(t1.x, m2, acc[i][1]); acc[i][1] = ffma2(t1.y, m3, acc[i][1]);
                t0 = __ldg(TBp + 4); t1 = __ldg(TBp + 5);
                acc[i][2] = ffma2(t0.x, m0, acc[i][2]); acc[i][2] = ffma2(t0.y, m1, acc[i][2]);
                acc[i][2] = ffma2(t1.x, m2, acc[i][2]); acc[i][2] = ffma2(t1.y, m3, acc[i][2]);
            }
        }
    }
    __syncthreads();   // release smid region for tile reuse

    // ---- phase 3: 16 quad chunks: stage out2 tile (bil of feat), conv ----
    for (int q = 0; q < 16; q++) {
        if (tid < 54) sTW[tid] = __ldg(g_TWq + q * 54 + tid);
        const ulonglong2* F = (const ulonglong2*)g_feat4 + q * 16384;
        for (int t = tid; t < 1188; t += 256) {
            float4 wv = sbilW[t];
            int meta = sMeta[t];
            int o00 = meta & 16383, dx = (meta >> 14) & 1, dy7 = ((meta >> 15) & 1) << 7;
            int o01 = o00 + dx, o10 = o00 + dy7, o11 = o10 + dx;
            ull w00 = pk2(wv.x, wv.x), w01 = pk2(wv.y, wv.y);
            ull w10 = pk2(wv.z, wv.z), w11 = pk2(wv.w, wv.w);
            ulonglong2 v00 = __ldg(F + o00), v01 = __ldg(F + o01);
            ulonglong2 v10 = __ldg(F + o10), v11 = __ldg(F + o11);
            ull lo = ffma2(w00, v00.x, 0ULL), hi = ffma2(w00, v00.y, 0ULL);
            lo = ffma2(w01, v01.x, lo); hi = ffma2(w01, v01.y, hi);
            lo = ffma2(w10, v10.x, lo); hi = ffma2(w10, v10.y, hi);
            lo = ffma2(w11, v11.x, lo); hi = ffma2(w11, v11.y, hi);
            tile[(meta >> 20) & 2047] = make_ulonglong2(lo, hi);
        }
        __syncthreads();
#pragma unroll
        for (int ky = 0; ky < 3; ky++) {
#pragma unroll
            for (int kx = 0; kx < 3; kx++) {
                const ull* W = sTW + (ky * 3 + kx) * 6;
                ull w0l = W[0], w0h = W[1], w1l = W[2], w1h = W[3], w2l = W[4], w2h = W[5];
#pragma unroll
                for (int i = 0; i < 4; i++) {
                    ulonglong2 v = tile[(4 * yt + i + ky) * 68 + xl + kx];
                    acc[i][0] = ffma2(w0l, v.x, acc[i][0]); acc[i][0] = ffma2(w0h, v.y, acc[i][0]);
                    acc[i][1] = ffma2(w1l, v.x, acc[i][1]); acc[i][1] = ffma2(w1h, v.y, acc[i][1]);
                    acc[i][2] = ffma2(w2l, v.x, acc[i][2]); acc[i][2] = ffma2(w2h, v.y, acc[i][2]);
                }
            }
        }
        __syncthreads();
    }

    float tb0 = __ldg(tb), tb1 = __ldg(tb + 1), tb2 = __ldg(tb + 2);
#pragma unroll
    for (int i = 0; i < 4; i++) {
        int yo = 4 * yt + i;
        float2 a0 = upk2(acc[i][0]), a1 = upk2(acc[i][1]), a2 = upk2(acc[i][2]);
        g_pred4[(y0 + yo) * 512 + x0 + xl] =
            make_float4(tb0 + a0.x + a0.y, tb1 + a1.x + a1.y, tb2 + a2.x + a2.y, 0.f);
    }
}

// ---------------- K5: query gather ----------------
__global__ void gather_kernel(const float* __restrict__ coord,
                              const float* __restrict__ cell,
                              float* __restrict__ out) {
    int q = blockIdx.x * 256 + threadIdx.x;
    float2 cd = __ldg((const float2*)coord + q);
    float2 cl = __ldg((const float2*)cell + q);
    const float LO = -0.999999f, HI = 0.999999f;
    float gyq = fminf(fmaxf(cd.x - cl.x * 0.5f + 1e-6f, LO), HI);
    float gxq = fminf(fmaxf(cd.y - cl.y * 0.5f + 1e-6f, LO), HI);
    int xi = (int)rintf((gxq + 1.0f) * 0.5f * 511.0f);
    int yi = (int)rintf((gyq + 1.0f) * 0.5f * 511.0f);
    xi = min(511, max(0, xi));
    yi = min(511, max(0, yi));
    float4 v = __ldg(&g_pred4[(yi << 9) + xi]);
    out[q * 3 + 0] = v.x;
    out[q * 3 + 1] = v.y;
    out[q * 3 + 2] = v.z;
}

// ---------------- launch ----------------
extern "C" void kernel_launch(void* const* d_in, const int* in_sizes, int n_in,
                              void* d_out, int out_size) {
    const float* inp   = (const float*)d_in[0];
    const float* coord = (const float*)d_in[1];
    const float* cell  = (const float*)d_in[2];
    const float* enc_w = (const float*)d_in[3];
    const float* enc_b = (const float*)d_in[4];
    const float* w1    = (const float*)d_in[5];
    const float* b1    = (const float*)d_in[6];
    const float* w2    = (const float*)d_in[7];
    const float* b2    = (const float*)d_in[8];
    const float* rw    = (const float*)d_in[9];
    const float* rb    = (const float*)d_in[10];
    const float* ow    = (const float*)d_in[11];
    const float* ob    = (const float*)d_in[12];
    const float* tw    = (const float*)d_in[13];
    const float* tb    = (const float*)d_in[14];
    const float* wc    = (const float*)d_in[15];
    const float* we    = (const float*)d_in[16];
    float* out = (float*)d_out;

    const int SHM = 19008 + 4752 + 38016;   // 61776 B
    cudaFuncSetAttribute(fused_kernel, cudaFuncAttributeMaxDynamicSharedMemorySize, SHM);

    enc_kernel<<<1024, 256>>>(inp, enc_w, enc_b);
    phase_kernel<<<16, 64>>>(w1, b1, w2, b2, rw, rb, ow, ob, wc, we);
    prep_kernel<<<186, 256>>>(tw);
    fused_kernel<<<dim3(8, 32), 256, SHM>>>(tb);
    gather_kernel<<<1024, 256>>>(coord, cell, out);
}

// round 16
// speedup vs baseline: 1.1086x; 1.0692x over previous
#include <cuda_runtime.h>
#include <math.h>

typedef unsigned long long ull;

// ---------------- f32x2 packed helpers (Blackwell) ----------------
__device__ __forceinline__ ull pk2(float lo, float hi) {
    ull r; asm("mov.b64 %0, {%1,%2};" : "=l"(r) : "f"(lo), "f"(hi)); return r;
}
__device__ __forceinline__ float2 upk2(ull v) {
    float2 r; asm("mov.b64 {%0,%1}, %2;" : "=f"(r.x), "=f"(r.y) : "l"(v)); return r;
}
__device__ __forceinline__ ull ffma2(ull a, ull b, ull c) {
    ull d; asm("fma.rn.f32x2 %0, %1, %2, %3;" : "=l"(d) : "l"(a), "l"(b), "l"(c)); return d;
}

// ---------------- device scratch ----------------
__device__ __align__(16) float4 g_feat4[16 * 16384];  // enc output, [quad][y][x] (4 ch)
__device__ __align__(16) float4 g_pred4[512 * 512];   // tail output, (r,g,b,_)
__device__ float g_off[32];                           // per-phase offsets
__device__ float g_A[16 * 512];                       // [ph][k][c]
__device__ float g_B[16 * 512];                       // [ph][c][k]
__device__ __align__(16) ull g_AF2[16 * 4 * 16384];   // A_ph @ feat, [ph][kpair][pos]
__device__ __align__(16) ull g_TB[1728];              // [ph][tap][o][kp] packed k-pairs
__device__ __align__(16) ull g_TWq[864];              // [q][tap][o][half] packed ch-pairs

// ---------------- K1: enc conv3x3, pad=1, 3->64 ch, quad output ----------------
__global__ void __launch_bounds__(256) enc_kernel(const float* __restrict__ inp,
                                                  const float* __restrict__ w,
                                                  const float* __restrict__ b) {
    __shared__ float sw[108];
    __shared__ float sb[4];
    int tid = threadIdx.x;
    int idx = blockIdx.x * 256 + tid;        // quad*16384 + y*128 + x
    int quad = idx >> 14;
    if (tid < 108) sw[tid] = w[quad * 108 + tid];
    if (tid < 4)   sb[tid] = b[quad * 4 + tid];
    __syncthreads();
    int rem = idx & 16383, y = rem >> 7, x = rem & 127;
    float a0 = sb[0], a1 = sb[1], a2 = sb[2], a3 = sb[3];
#pragma unroll
    for (int ci = 0; ci < 3; ci++) {
        const float* ip = inp + ci * 16384;
#pragma unroll
        for (int ky = 0; ky < 3; ky++) {
            int yy = y + ky - 1;
            if (yy < 0 || yy > 127) continue;
#pragma unroll
            for (int kx = 0; kx < 3; kx++) {
                int xx = x + kx - 1;
                if (xx < 0 || xx > 127) continue;
                float v = __ldg(ip + yy * 128 + xx);
                int t = ci * 9 + ky * 3 + kx;
                a0 += v * sw[t]; a1 += v * sw[27 + t];
                a2 += v * sw[54 + t]; a3 += v * sw[81 + t];
            }
        }
    }
    g_feat4[idx] = make_float4(a0, a1, a2, a3);
}

// ---------------- K2: per-phase MLP -> off, A, B ----------------
__global__ void phase_kernel(const float* __restrict__ w1, const float* __restrict__ b1,
                             const float* __restrict__ w2, const float* __restrict__ b2,
                             const float* __restrict__ rw, const float* __restrict__ rb,
                             const float* __restrict__ ow, const float* __restrict__ ob,
                             const float* __restrict__ wc, const float* __restrict__ we) {
    __shared__ float s1[64], s2[64], sr[4];
    int c = threadIdx.x;
    int ph = blockIdx.x;                 // ph = (y%4)*4 + (x%4)
    float chv = ((ph >> 2) + 0.5f) * 0.25f - 0.5f;
    float cwv = ((ph & 3)  + 0.5f) * 0.25f - 0.5f;
    float e1 = b1[c] + w1[c * 4 + 0] * 0.25f + w1[c * 4 + 1] * 0.25f
                     + w1[c * 4 + 2] * chv   + w1[c * 4 + 3] * cwv;
    s1[c] = fmaxf(e1, 0.f);
    __syncthreads();
    float e2 = b2[c];
    for (int d = 0; d < 64; d++) e2 += w2[c * 64 + d] * s1[d];
    s2[c] = fmaxf(e2, 0.f);
    __syncthreads();
    if (c < 4) {
        float z = rb[c];
        for (int d = 0; d < 64; d++) z += rw[c * 64 + d] * s2[d];
        sr[c] = 1.f / (1.f + expf(-z));
    } else if (c < 6) {
        int o = c - 4;
        float z = ob[o];
        for (int d = 0; d < 64; d++) z += ow[o * 64 + d] * s2[d];
        g_off[ph * 2 + o] = z;
    }
    __syncthreads();
    float r0 = sr[0], r1 = sr[1], r2 = sr[2], r3 = sr[3];
    for (int t = c; t < 512; t += 64) {
        g_A[ph * 512 + t] = r0 * wc[t] + r1 * wc[512 + t] + r2 * wc[1024 + t] + r3 * wc[1536 + t];
        g_B[ph * 512 + t] = r0 * we[t] + r1 * we[512 + t] + r2 * we[1024 + t] + r3 * we[1536 + t];
    }
}

// ---------------- K2b: AF[ph][kpair][pos] = packed A_ph @ feat (1024 blocks, machine-filling) ----------------
__global__ void __launch_bounds__(256) af_kernel() {
    __shared__ ull sA2[256];                 // [k][cpair] for this phase
    int tid = threadIdx.x;
    int ph = blockIdx.x >> 6;                // 16 phases x 64 chunks
    int chunk = blockIdx.x & 63;
    sA2[tid] = ((const ull*)g_A)[ph * 256 + tid];
    __syncthreads();
    int pos = chunk * 256 + tid;

    ull f2[32];
    const ulonglong2* F = (const ulonglong2*)g_feat4;
#pragma unroll
    for (int qd = 0; qd < 16; qd++) {
        ulonglong2 v = __ldg(F + qd * 16384 + pos);
        f2[2 * qd] = v.x; f2[2 * qd + 1] = v.y;
    }
    float m[8];
#pragma unroll
    for (int k = 0; k < 8; k++) {
        ull acc = 0ULL;
#pragma unroll
        for (int i = 0; i < 32; i++) acc = ffma2(sA2[k * 32 + i], f2[i], acc);
        float2 a = upk2(acc);
        m[k] = a.x + a.y;
    }
#pragma unroll
    for (int kp = 0; kp < 4; kp++)
        g_AF2[(ph * 4 + kp) * 16384 + pos] = pk2(m[2 * kp], m[2 * kp + 1]);
}

// ---------------- K2c: parallel pack: TB (8 subs/elem, proven) + quad tail weights ----------------
__global__ void __launch_bounds__(256) pack_kernel(const float* __restrict__ tw) {
    int blk = blockIdx.x;
    int tid = threadIdx.x;
    if (blk < 54) {
        int gt = blk * 256 + tid;
        int e = gt >> 3;              // element 0..1727
        int sub = gt & 7;
        // e = ph*108 + tap*12 + o*4 + kp
        int kp = e & 3, o = (e >> 2) % 3, tap = (e / 12) % 9, ph = e / 108;
        float lo = 0.f, hi = 0.f;
        const float* Bp = g_B + ph * 512;
#pragma unroll
        for (int j = 0; j < 8; j++) {
            int c = sub * 8 + j;
            float wv = __ldg(tw + o * 576 + c * 9 + tap);
            lo += wv * Bp[c * 8 + 2 * kp];
            hi += wv * Bp[c * 8 + 2 * kp + 1];
        }
#pragma unroll
        for (int d = 4; d > 0; d >>= 1) {
            lo += __shfl_down_sync(0xffffffffu, lo, d);
            hi += __shfl_down_sync(0xffffffffu, hi, d);
        }
        if (sub == 0) g_TB[e] = pk2(lo, hi);
    } else {
        int u = (blk - 54) * 256 + tid;       // ((q*9+tap)*3+o)*2+h
        if (u < 864) {
            int h = u & 1, o = (u >> 1) % 3, tap = (u / 6) % 9, q = u / 54;
            int c0 = 4 * q + 2 * h;
            g_TWq[u] = pk2(__ldg(tw + o * 576 + c0 * 9 + tap),
                           __ldg(tw + o * 576 + (c0 + 1) * 9 + tap));
        }
    }
}

// ---------------- K3: FUSED out2 + tail conv, double-buffered phase 3 ----------------
// block: 64x16 output tile; halo 66x18 = 1188 px; 16 quad chunks, 2 tile buffers.
__global__ void __launch_bounds__(256, 3) fused_kernel(const float* __restrict__ tb) {
    extern __shared__ __align__(16) char shm[];
    float4* sbilW = (float4*)shm;                     // [1188]  19008 B
    int*    sMeta = (int*)(shm + 19008);              // [1188]   4752 B
    ull*    smid  = (ull*)(shm + 23760);              // [4*1188] 38016 B (union)
    ulonglong2* tile0 = (ulonglong2*)(shm + 23760);           // [18*68] (union)
    ulonglong2* tile1 = (ulonglong2*)(shm + 23760 + 19584);   // [18*68]
    ull*    sTW   = (ull*)(shm + 23760 + 39168);      // [2][54]

    int tid = threadIdx.x;
    int x0 = blockIdx.x * 64, y0 = blockIdx.y * 16;
    int xl = tid & 63, yt = tid >> 6;

    // ---- phase 1a: bilinear staging for halo pixels ----
    for (int t = tid; t < 1188; t += 256) {
        int r = t / 66, cc = t - r * 66;
        int yy = y0 - 1 + r, xx = x0 - 1 + cc;
        float4 wv = make_float4(0.f, 0.f, 0.f, 0.f);
        int meta = (r * 68 + cc) << 20;
        if (yy >= 0 && yy < 512 && xx >= 0 && xx < 512) {
            int ph = ((yy & 3) << 2) | (xx & 3);
            float offx = __ldg(g_off + 2 * ph), offy = __ldg(g_off + 2 * ph + 1);
            const float C2 = 2.0f / 127.0f;
            float gx = ((xx + 0.5f) * 0.25f - 0.5f) * C2 - 1.0f + offx * C2;
            float gy = ((yy + 0.5f) * 0.25f - 0.5f) * C2 - 1.0f + offy * C2;
            float px = (gx + 1.0f) * 63.5f;
            float py = (gy + 1.0f) * 63.5f;
            float fx = floorf(px), fy = floorf(py);
            float wx1 = px - fx, wx0 = 1.f - wx1;
            float wy1 = py - fy, wy0 = 1.f - wy1;
            int ix0 = (int)fx, iy0 = (int)fy;
            float mx0 = (ix0 >= 0 && ix0 < 128) ? 1.f : 0.f;
            float mx1 = (ix0 + 1 >= 0 && ix0 + 1 < 128) ? 1.f : 0.f;
            float my0 = (iy0 >= 0 && iy0 < 128) ? 1.f : 0.f;
            float my1 = (iy0 + 1 >= 0 && iy0 + 1 < 128) ? 1.f : 0.f;
            int cx0 = min(127, max(0, ix0)), cx1 = min(127, max(0, ix0 + 1));
            int cy0 = min(127, max(0, iy0)), cy1 = min(127, max(0, iy0 + 1));
            wv = make_float4(wy0 * wx0 * my0 * mx0, wy0 * wx1 * my0 * mx1,
                             wy1 * wx0 * my1 * mx0, wy1 * wx1 * my1 * mx1);
            int o00 = (cy0 << 7) | cx0;
            meta |= o00 | ((cx1 - cx0) << 14) | ((cy1 - cy0) << 15) | (ph << 16);
        }
        sbilW[t] = wv;
        sMeta[t] = meta;
    }
    __syncthreads();

    // ---- phase 1b: mid halo = bilinear(AF) ----
    for (int t = tid; t < 1188; t += 256) {
        float4 wv = sbilW[t];
        int meta = sMeta[t];
        int o00 = meta & 16383, dx = (meta >> 14) & 1, dy7 = ((meta >> 15) & 1) << 7;
        int ph = (meta >> 16) & 15;
        ull w00 = pk2(wv.x, wv.x), w01 = pk2(wv.y, wv.y);
        ull w10 = pk2(wv.z, wv.z), w11 = pk2(wv.w, wv.w);
        int o01 = o00 + dx, o10 = o00 + dy7, o11 = o10 + dx;
        const ull* AFp = g_AF2 + ph * 4 * 16384;
#pragma unroll
        for (int kp = 0; kp < 4; kp++) {
            const ull* Q = AFp + kp * 16384;
            ull a = ffma2(w00, __ldg(Q + o00), 0ULL);
            ull bq = ffma2(w01, __ldg(Q + o01), 0ULL);
            a = ffma2(w10, __ldg(Q + o10), a);
            bq = ffma2(w11, __ldg(Q + o11), bq);
            float2 s1 = upk2(a), s2 = upk2(bq);
            smid[kp * 1188 + t] = pk2(s1.x + s2.x, s1.y + s2.y);
        }
    }
    __syncthreads();

    // ---- phase 2: mid-conv via TB (rank-8 correction folded into tail) ----
    ull acc[4][3];
#pragma unroll
    for (int i = 0; i < 4; i++)
#pragma unroll
        for (int o = 0; o < 3; o++) acc[i][o] = 0ULL;
#pragma unroll
    for (int i = 0; i < 4; i++) {
        int yo = 4 * yt + i;
#pragma unroll
        for (int ky = 0; ky < 3; ky++) {
#pragma unroll
            for (int kx = 0; kx < 3; kx++) {
                int hidx = (yo + ky) * 66 + xl + kx;
                int ph = (sMeta[hidx] >> 16) & 15;
                const ulonglong2* TBp = (const ulonglong2*)(g_TB + ph * 108 + (ky * 3 + kx) * 12);
                ull m0 = smid[hidx], m1 = smid[1188 + hidx];
                ull m2 = smid[2376 + hidx], m3 = smid[3564 + hidx];
                ulonglong2 t0 = __ldg(TBp + 0), t1 = __ldg(TBp + 1);
                acc[i][0] = ffma2(t0.x, m0, acc[i][0]); acc[i][0] = ffma2(t0.y, m1, acc[i][0]);
                acc[i][0] = ffma2(t1.x, m2, acc[i][0]); acc[i][0] = ffma2(t1.y, m3, acc[i][0]);
                t0 = __ldg(TBp + 2); t1 = __ldg(TBp + 3);
                acc[i][1] = ffma2(t0.x, m0, acc[i][1]); acc[i][1] = ffma2(t0.y, m1, acc[i][1]);
                acc[i][1] = ffma2(t1.x, m2, acc[i][1]); acc[i][1] = ffma2(t1.y, m3, acc[i][1]);
                t0 = __ldg(TBp + 4); t1 = __ldg(TBp + 5);
                acc[i][2] = ffma2(t0.x, m0, acc[i][2]); acc[i][2] = ffma2(t0.y, m1, acc[i][2]);
                acc[i][2] = ffma2(t1.x, m2, acc[i][2]); acc[i][2] = ffma2(t1.y, m3, acc[i][2]);
            }
        }
    }
    __syncthreads();   // release smid region for tile reuse

    // ---- phase 3: 16 quad chunks, double-buffered: stage q+1 while convolving q ----
    // stage quad 0 into tile0 + its weights
    {
        if (tid < 54) sTW[tid] = __ldg(g_TWq + tid);
        const ulonglong2* F = (const ulonglong2*)g_feat4;
        for (int t = tid; t < 1188; t += 256) {
            float4 wv = sbilW[t];
            int meta = sMeta[t];
            int o00 = meta & 16383, dx = (meta >> 14) & 1, dy7 = ((meta >> 15) & 1) << 7;
            int o01 = o00 + dx, o10 = o00 + dy7, o11 = o10 + dx;
            ull w00 = pk2(wv.x, wv.x), w01 = pk2(wv.y, wv.y);
            ull w10 = pk2(wv.z, wv.z), w11 = pk2(wv.w, wv.w);
            ulonglong2 v00 = __ldg(F + o00), v01 = __ldg(F + o01);
            ulonglong2 v10 = __ldg(F + o10), v11 = __ldg(F + o11);
            ull lo = ffma2(w00, v00.x, 0ULL), hi = ffma2(w00, v00.y, 0ULL);
            lo = ffma2(w01, v01.x, lo); hi = ffma2(w01, v01.y, hi);
            lo = ffma2(w10, v10.x, lo); hi = ffma2(w10, v10.y, hi);
            lo = ffma2(w11, v11.x, lo); hi = ffma2(w11, v11.y, hi);
            tile0[(meta >> 20) & 2047] = make_ulonglong2(lo, hi);
        }
        __syncthreads();
    }

    for (int q = 0; q < 16; q++) {
        ulonglong2* cur = (q & 1) ? tile1 : tile0;
        ulonglong2* nxt = (q & 1) ? tile0 : tile1;
        // stage quad q+1 into the other buffer (overlaps with conv below)
        if (q < 15) {
            if (tid < 54) sTW[((q + 1) & 1) * 54 + tid] = __ldg(g_TWq + (q + 1) * 54 + tid);
            const ulonglong2* F = (const ulonglong2*)g_feat4 + (q + 1) * 16384;
            for (int t = tid; t < 1188; t += 256) {
                float4 wv = sbilW[t];
                int meta = sMeta[t];
                int o00 = meta & 16383, dx = (meta >> 14) & 1, dy7 = ((meta >> 15) & 1) << 7;
                int o01 = o00 + dx, o10 = o00 + dy7, o11 = o10 + dx;
                ull w00 = pk2(wv.x, wv.x), w01 = pk2(wv.y, wv.y);
                ull w10 = pk2(wv.z, wv.z), w11 = pk2(wv.w, wv.w);
                ulonglong2 v00 = __ldg(F + o00), v01 = __ldg(F + o01);
                ulonglong2 v10 = __ldg(F + o10), v11 = __ldg(F + o11);
                ull lo = ffma2(w00, v00.x, 0ULL), hi = ffma2(w00, v00.y, 0ULL);
                lo = ffma2(w01, v01.x, lo); hi = ffma2(w01, v01.y, hi);
                lo = ffma2(w10, v10.x, lo); hi = ffma2(w10, v10.y, hi);
                lo = ffma2(w11, v11.x, lo); hi = ffma2(w11, v11.y, hi);
                nxt[(meta >> 20) & 2047] = make_ulonglong2(lo, hi);
            }
        }
        // conv quad q from cur
        const ull* W0 = sTW + (q & 1) * 54;
#pragma unroll
        for (int ky = 0; ky < 3; ky++) {
#pragma unroll
            for (int kx = 0; kx < 3; kx++) {
                const ull* W = W0 + (ky * 3 + kx) * 6;
                ull w0l = W[0], w0h = W[1], w1l = W[2], w1h = W[3], w2l = W[4], w2h = W[5];
#pragma unroll
                for (int i = 0; i < 4; i++) {
                    ulonglong2 v = cur[(4 * yt + i + ky) * 68 + xl + kx];
                    acc[i][0] = ffma2(w0l, v.x, acc[i][0]); acc[i][0] = ffma2(w0h, v.y, acc[i][0]);
                    acc[i][1] = ffma2(w1l, v.x, acc[i][1]); acc[i][1] = ffma2(w1h, v.y, acc[i][1]);
                    acc[i][2] = ffma2(w2l, v.x, acc[i][2]); acc[i][2] = ffma2(w2h, v.y, acc[i][2]);
                }
            }
        }
        __syncthreads();
    }

    float tb0 = __ldg(tb), tb1 = __ldg(tb + 1), tb2 = __ldg(tb + 2);
#pragma unroll
    for (int i = 0; i < 4; i++) {
        int yo = 4 * yt + i;
        float2 a0 = upk2(acc[i][0]), a1 = upk2(acc[i][1]), a2 = upk2(acc[i][2]);
        g_pred4[(y0 + yo) * 512 + x0 + xl] =
            make_float4(tb0 + a0.x + a0.y, tb1 + a1.x + a1.y, tb2 + a2.x + a2.y, 0.f);
    }
}

// ---------------- K5: query gather ----------------
__global__ void gather_kernel(const float* __restrict__ coord,
                              const float* __restrict__ cell,
                              float* __restrict__ out) {
    int q = blockIdx.x * 256 + threadIdx.x;
    float2 cd = __ldg((const float2*)coord + q);
    float2 cl = __ldg((const float2*)cell + q);
    const float LO = -0.999999f, HI = 0.999999f;
    float gyq = fminf(fmaxf(cd.x - cl.x * 0.5f + 1e-6f, LO), HI);
    float gxq = fminf(fmaxf(cd.y - cl.y * 0.5f + 1e-6f, LO), HI);
    int xi = (int)rintf((gxq + 1.0f) * 0.5f * 511.0f);
    int yi = (int)rintf((gyq + 1.0f) * 0.5f * 511.0f);
    xi = min(511, max(0, xi));
    yi = min(511, max(0, yi));
    float4 v = __ldg(&g_pred4[(yi << 9) + xi]);
    out[q * 3 + 0] = v.x;
    out[q * 3 + 1] = v.y;
    out[q * 3 + 2] = v.z;
}

// ---------------- launch ----------------
extern "C" void kernel_launch(void* const* d_in, const int* in_sizes, int n_in,
                              void* d_out, int out_size) {
    const float* inp   = (const float*)d_in[0];
    const float* coord = (const float*)d_in[1];
    const float* cell  = (const float*)d_in[2];
    const float* enc_w = (const float*)d_in[3];
    const float* enc_b = (const float*)d_in[4];
    const float* w1    = (const float*)d_in[5];
    const float* b1    = (const float*)d_in[6];
    const float* w2    = (const float*)d_in[7];
    const float* b2    = (const float*)d_in[8];
    const float* rw    = (const float*)d_in[9];
    const float* rb    = (const float*)d_in[10];
    const float* ow    = (const float*)d_in[11];
    const float* ob    = (const float*)d_in[12];
    const float* tw    = (const float*)d_in[13];
    const float* tb    = (const float*)d_in[14];
    const float* wc    = (const float*)d_in[15];
    const float* we    = (const float*)d_in[16];
    float* out = (float*)d_out;

    const int SHM = 23760 + 39168 + 864;   // 63792 B
    cudaFuncSetAttribute(fused_kernel, cudaFuncAttributeMaxDynamicSharedMemorySize, SHM);

    enc_kernel<<<1024, 256>>>(inp, enc_w, enc_b);
    phase_kernel<<<16, 64>>>(w1, b1, w2, b2, rw, rb, ow, ob, wc, we);
    af_kernel<<<1024, 256>>>();
    pack_kernel<<<58, 256>>>(tw);
    fused_kernel<<<dim3(8, 32), 256, SHM>>>(tb);
    gather_kernel<<<1024, 256>>>(coord, cell, out);
}